// round 4
// baseline (speedup 1.0000x reference)
#include <cuda_runtime.h>

// WaveletTransformLayer: x (B=128, T=2048, F=32) fp32.
// 3-level moving-average pyramid (w = 2, 4, 8) per (b,f) series.
// Levels 1+2 fused (m2 computed directly from x with weights 1,2,2,2,1 /8),
// float4 smem traffic throughout, conflict-free float4 transpose (stride 148).

constexpr int B = 128;
constexpr int T = 2048;
constexpr int F = 32;

constexpr int N1 = T - 1;                  // 2047
constexpr int N2 = N1 - 3;                 // 2044
constexpr int N3 = N2 - 7;                 // 2037
constexpr int OUT_PER = N1 + N2 + 2 * N3;  // 8165

constexpr int TT = 128;                    // time-tile (outputs per tile per stream)
constexpr int NTILES = T / TT;             // 16
constexpr int XGROUPS = 36;                // x rows loaded: 144 = covers index 4*33+8=140
constexpr int ST  = 148;                   // s_x row stride (floats); ==4 mod 8 -> conflict-free STS.128 transpose
constexpr int SM2 = 136;                   // s_m2 row stride; m2 local indices 0..135

__device__ __forceinline__ void passA_group(
    const float* __restrict__ rx, float* __restrict__ rm,
    float* __restrict__ op, int t0, int G, bool emit, float invT)
{
    const int j0 = 4 * G;
    const float4 A = *(const float4*)&rx[j0];
    const float4 Bv = *(const float4*)&rx[j0 + 4];
    const float x8 = rx[j0 + 8];
    const float xv[9] = {A.x, A.y, A.z, A.w, Bv.x, Bv.y, Bv.z, Bv.w, x8};

    // m2[j] = (x[j] + 2(x[j+1]+x[j+2]+x[j+3]) + x[j+4]) / 8
    float m[4];
    #pragma unroll
    for (int c = 0; c < 4; c++) {
        float s = (xv[c] + xv[c + 4]) + 2.0f * ((xv[c + 1] + xv[c + 2]) + xv[c + 3]);
        m[c] = s * 0.125f;
    }
    *(float4*)&rm[j0] = make_float4(m[0], m[1], m[2], m[3]);

    if (emit) {
        const float hInvT = 0.5f * invT;
        #pragma unroll
        for (int c = 0; c < 4; c++) {
            const int t = t0 + j0 + c;
            // d1[t] = (x[t+1]-x[t])/2
            if (t < N1) op[t] = (xv[c + 1] - xv[c]) * hInvT;
            // d2[t] = m1[t+3] - m2[t],  m1[t+3] = (x[t+3]+x[t+4])/2
            if (t < N2) op[N1 + t] = ((xv[c + 3] + xv[c + 4]) * 0.5f - m[c]) * invT;
        }
    }
}

__global__ __launch_bounds__(256, 6)
void wavelet_kernel(const float* __restrict__ x, float* __restrict__ out) {
    __shared__ float s_x[F * ST];    // transposed x tile (+halo), per-feature rows
    __shared__ float s_m2[F * SM2];  // level-2 moving averages

    const int tile = blockIdx.x & (NTILES - 1);
    const int b    = blockIdx.x >> 4;
    const int t0   = tile * TT;
    const int lane = threadIdx.x & 31;
    const int w    = threadIdx.x >> 5;       // warp id, 0..7

    const float invT = 1.0f / (float)T;
    const float* xp = x + ((size_t)b * T + t0) * F;

    // ---- Coalesced load + float4 transpose ----
    // Row-group g: rows 4g..4g+3 (time), lane = feature. 4 coalesced LDG per
    // group, then one STS.128 per lane: s_x[lane][4g..4g+3]. Stride 148
    // (==4 mod 8) -> the 32 16B stores tile all 32 banks: conflict-free.
    for (int g = w; g < XGROUPS; g += 8) {
        const int r0 = 4 * g;
        float v0 = (t0 + r0     < T) ? xp[(size_t)(r0    ) * F + lane] : 0.0f;
        float v1 = (t0 + r0 + 1 < T) ? xp[(size_t)(r0 + 1) * F + lane] : 0.0f;
        float v2 = (t0 + r0 + 2 < T) ? xp[(size_t)(r0 + 2) * F + lane] : 0.0f;
        float v3 = (t0 + r0 + 3 < T) ? xp[(size_t)(r0 + 3) * F + lane] : 0.0f;
        *(float4*)&s_x[lane * ST + r0] = make_float4(v0, v1, v2, v3);
    }
    __syncthreads();

    // ---- Warp-private pyramid: warp w owns features 4w .. 4w+3 ----
    #pragma unroll
    for (int ff = 0; ff < 4; ff++) {
        const int f = (w << 2) + ff;
        const float* __restrict__ rx = s_x + f * ST;
        float* __restrict__ rm = s_m2 + f * SM2;
        float* __restrict__ op = out + (size_t)(b * F + f) * OUT_PER;

        // Pass A: fused levels 1+2. Groups 0..33 (m2 local 0..135).
        passA_group(rx, rm, op, t0, lane, true, invT);
        if (lane < 2)
            passA_group(rx, rm, op, t0, 32 + lane, false, invT);
        __syncwarp();

        // Pass B: level 3 (w=8 over m2). Group = lane, outputs j0..j0+3.
        {
            const int j0 = 4 * lane;
            const float4 A = *(const float4*)&rm[j0];
            const float4 Bv = *(const float4*)&rm[j0 + 4];
            const float4 C = *(const float4*)&rm[j0 + 8];
            const float mv[12] = {A.x, A.y, A.z, A.w,
                                  Bv.x, Bv.y, Bv.z, Bv.w,
                                  C.x, C.y, C.z, C.w};
            float s = ((mv[0] + mv[1]) + (mv[2] + mv[3]))
                    + ((mv[4] + mv[5]) + (mv[6] + mv[7]));
            #pragma unroll
            for (int c = 0; c < 4; c++) {
                const float m3 = s * 0.125f;
                const int t = t0 + j0 + c;
                if (t < N3) {
                    op[N1 + N2 + t]      = (mv[c + 7] - m3) * invT;
                    op[N1 + N2 + N3 + t] = m3 * invT;
                }
                if (c < 3) s += mv[c + 8] - mv[c];
            }
        }
        __syncwarp();
    }
}

extern "C" void kernel_launch(void* const* d_in, const int* in_sizes, int n_in,
                              void* d_out, int out_size) {
    const float* x = (const float*)d_in[0];
    float* out = (float*)d_out;
    wavelet_kernel<<<B * NTILES, 256>>>(x, out);
}

// round 5
// speedup vs baseline: 1.5549x; 1.5549x over previous
#include <cuda_runtime.h>

// WaveletTransformLayer: x (B=128, T=2048, F=32) fp32.
// 3-level moving-average pyramid (w = 2, 4, 8) per (b,f) series.
// Fast path: lane owns an ALIGNED run of 4 outputs per section (alignment
// shift oA/oB is compile-time per f&3), so all output stores are STG.128
// and all smem reads are LDS.128 — minimal L1 wavefronts. Last tile uses a
// scalar fallback for boundary gating.

constexpr int B = 128;
constexpr int T = 2048;
constexpr int F = 32;

constexpr int N1 = T - 1;                  // 2047
constexpr int N2 = N1 - 3;                 // 2044
constexpr int N3 = N2 - 7;                 // 2037
constexpr int OUT_PER = N1 + N2 + 2 * N3;  // 8165

constexpr int TT = 128;                    // time-tile
constexpr int NTILES = T / TT;             // 16
constexpr int XG = 37;                     // x float4-groups per row: fills [0,148)
constexpr int ST = 156;                    // s_x row stride (16B-aligned, ==4 mod 8)
constexpr int SM2 = 140;                   // s_m2 row stride (16B-aligned, ==4 mod 8)

// Store a float4-run at aligned offset O (compile-time). Lanes 0..30 vector;
// lane 31 stores only the in-range first 4-O components; O==0 -> all vector.
template<int O>
__device__ __forceinline__ void store_vec(float* __restrict__ sec, int lane, const float4& v) {
    if (O == 0) {
        *reinterpret_cast<float4*>(sec + 4 * lane) = v;
    } else {
        const float* pv = &v.x;
        if (lane < 31) {
            *reinterpret_cast<float4*>(sec + O + 4 * lane) = v;
        } else {
            #pragma unroll
            for (int c = 0; c < 4 - O; c++) sec[O + 124 + c] = pv[c];
        }
    }
}

template<int OA, int OB>
__device__ __forceinline__ void feat_fast(const float* __restrict__ rx,
                                          float* __restrict__ rm,
                                          float* __restrict__ op,
                                          int t0, int lane, float invT) {
    const float hInvT = 0.5f * invT;

    // ---- Pass A: window x[4l .. 4l+12) ----
    float xw[12];
    *(float4*)&xw[0] = *(const float4*)(rx + 4 * lane);
    *(float4*)&xw[4] = *(const float4*)(rx + 4 * lane + 4);
    *(float4*)&xw[8] = *(const float4*)(rx + 4 * lane + 8);

    // aligned m2 group g = lane  (m2[j] = (x[j]+x[j+4]+2(x[j+1..j+3]))/8)
    {
        float4 m; float* pm = &m.x;
        #pragma unroll
        for (int c = 0; c < 4; c++)
            pm[c] = (xw[c] + xw[c + 4] + 2.0f * ((xw[c + 1] + xw[c + 2]) + xw[c + 3])) * 0.125f;
        *(float4*)(rm + 4 * lane) = m;
    }
    // extra m2 groups 32..34 (halo for pass B windows, up to m2[139])
    if (lane < 3) {
        const int g = 32 + lane;
        float xe[12];
        *(float4*)&xe[0] = *(const float4*)(rx + 4 * g);
        *(float4*)&xe[4] = *(const float4*)(rx + 4 * g + 4);
        *(float4*)&xe[8] = *(const float4*)(rx + 4 * g + 8);
        float4 m; float* pm = &m.x;
        #pragma unroll
        for (int c = 0; c < 4; c++)
            pm[c] = (xe[c] + xe[c + 4] + 2.0f * ((xe[c + 1] + xe[c + 2]) + xe[c + 3])) * 0.125f;
        *(float4*)(rm + 4 * g) = m;
    }

    // d1 at shift OA: d1[j] = (x[j+1]-x[j])/2
    {
        float4 v; float* pv = &v.x;
        #pragma unroll
        for (int c = 0; c < 4; c++)
            pv[c] = (xw[OA + c + 1] - xw[OA + c]) * hInvT;
        store_vec<OA>(op + t0, lane, v);
        if (OA > 0 && lane == 0) {
            #pragma unroll
            for (int c = 0; c < OA; c++)
                op[t0 + c] = (xw[c + 1] - xw[c]) * hInvT;
        }
    }
    // d2 at shift OB: d2[j] = (x[j+3]+x[j+4])/2 - m2[j]
    {
        float4 v; float* pv = &v.x;
        #pragma unroll
        for (int c = 0; c < 4; c++) {
            float m2s = (xw[OB + c] + xw[OB + c + 4]
                       + 2.0f * ((xw[OB + c + 1] + xw[OB + c + 2]) + xw[OB + c + 3])) * 0.125f;
            pv[c] = ((xw[OB + c + 3] + xw[OB + c + 4]) * 0.5f - m2s) * invT;
        }
        store_vec<OB>(op + N1 + t0, lane, v);
        if (OB > 0 && lane == 0) {
            #pragma unroll
            for (int c = 0; c < OB; c++) {
                float m2s = (xw[c] + xw[c + 4]
                           + 2.0f * ((xw[c + 1] + xw[c + 2]) + xw[c + 3])) * 0.125f;
                op[N1 + t0 + c] = ((xw[c + 3] + xw[c + 4]) * 0.5f - m2s) * invT;
            }
        }
    }
    __syncwarp();

    // ---- Pass B: window m2[4l .. 4l+12/16) ----
    constexpr int MAXO = (OA > OB) ? OA : OB;
    constexpr int MINO = (OA < OB) ? OA : OB;
    constexpr int NW = (MAXO >= 2) ? 16 : 12;
    float mw[NW];
    *(float4*)&mw[0] = *(const float4*)(rm + 4 * lane);
    *(float4*)&mw[4] = *(const float4*)(rm + 4 * lane + 4);
    *(float4*)&mw[8] = *(const float4*)(rm + 4 * lane + 8);
    if constexpr (MAXO >= 2)
        *(float4*)&mw[12] = *(const float4*)(rm + 4 * lane + 12);

    // sliding window-8 sums for positions MINO .. MAXO+3
    constexpr int NS = MAXO + 3 - MINO + 1;
    float s[NS];
    s[0] = ((mw[MINO] + mw[MINO + 1]) + (mw[MINO + 2] + mw[MINO + 3]))
         + ((mw[MINO + 4] + mw[MINO + 5]) + (mw[MINO + 6] + mw[MINO + 7]));
    #pragma unroll
    for (int i = 1; i < NS; i++)
        s[i] = s[i - 1] + mw[MINO + i + 7] - mw[MINO + i - 1];

    // d3 at shift OB: d3[j] = m2[j+7] - sum8/8
    {
        float4 v; float* pv = &v.x;
        #pragma unroll
        for (int c = 0; c < 4; c++)
            pv[c] = (mw[OB + c + 7] - s[OB + c - MINO] * 0.125f) * invT;
        store_vec<OB>(op + N1 + N2 + t0, lane, v);
        if (OB > 0 && lane == 0) {
            #pragma unroll
            for (int c = 0; c < OB; c++) {
                float sh = ((mw[c] + mw[c + 1]) + (mw[c + 2] + mw[c + 3]))
                         + ((mw[c + 4] + mw[c + 5]) + (mw[c + 6] + mw[c + 7]));
                op[N1 + N2 + t0 + c] = (mw[c + 7] - sh * 0.125f) * invT;
            }
        }
    }
    // a3 at shift OA: sum8/8
    {
        float4 v; float* pv = &v.x;
        #pragma unroll
        for (int c = 0; c < 4; c++)
            pv[c] = s[OA + c - MINO] * 0.125f * invT;
        store_vec<OA>(op + N1 + N2 + N3 + t0, lane, v);
        if (OA > 0 && lane == 0) {
            #pragma unroll
            for (int c = 0; c < OA; c++) {
                float sh = ((mw[c] + mw[c + 1]) + (mw[c + 2] + mw[c + 3]))
                         + ((mw[c + 4] + mw[c + 5]) + (mw[c + 6] + mw[c + 7]));
                op[N1 + N2 + N3 + t0 + c] = sh * 0.125f * invT;
            }
        }
    }
}

// Scalar fallback for the last tile (boundary gating), R3-style coalesced.
__device__ void feat_slow(const float* __restrict__ rx, float* __restrict__ rm,
                          float* __restrict__ op, int t0, int lane, float invT) {
    const float h = 0.5f * invT;
    for (int j = lane; j < N1 - t0; j += 32)
        op[t0 + j] = (rx[j + 1] - rx[j]) * h;
    for (int j = lane; j < N2 - t0; j += 32) {
        float m2 = (rx[j] + rx[j + 4] + 2.0f * ((rx[j + 1] + rx[j + 2]) + rx[j + 3])) * 0.125f;
        rm[j] = m2;
        op[N1 + t0 + j] = ((rx[j + 3] + rx[j + 4]) * 0.5f - m2) * invT;
    }
    __syncwarp();
    for (int j = lane; j < N3 - t0; j += 32) {
        float ss = ((rm[j] + rm[j + 1]) + (rm[j + 2] + rm[j + 3]))
                 + ((rm[j + 4] + rm[j + 5]) + (rm[j + 6] + rm[j + 7]));
        float m3 = ss * 0.125f;
        op[N1 + N2 + t0 + j]      = (rm[j + 7] - m3) * invT;
        op[N1 + N2 + N3 + t0 + j] = m3 * invT;
    }
}

__global__ __launch_bounds__(256, 5)
void wavelet_kernel(const float* __restrict__ x, float* __restrict__ out) {
    __shared__ float s_x[F * ST];
    __shared__ float s_m2[F * SM2];

    const int tile = blockIdx.x & (NTILES - 1);
    const int b    = blockIdx.x >> 4;
    const int t0   = tile * TT;
    const int lane = threadIdx.x & 31;
    const int w    = threadIdx.x >> 5;
    const float invT = 1.0f / (float)T;

    // Coalesced load + float4 transpose: rows = time, lane = feature.
    const float* xp = x + ((size_t)b * T + t0) * F;
    for (int g = w; g < XG; g += 8) {
        const int r0 = 4 * g;
        float v0 = (t0 + r0     < T) ? xp[(size_t)(r0    ) * F + lane] : 0.0f;
        float v1 = (t0 + r0 + 1 < T) ? xp[(size_t)(r0 + 1) * F + lane] : 0.0f;
        float v2 = (t0 + r0 + 2 < T) ? xp[(size_t)(r0 + 2) * F + lane] : 0.0f;
        float v3 = (t0 + r0 + 3 < T) ? xp[(size_t)(r0 + 3) * F + lane] : 0.0f;
        *(float4*)&s_x[lane * ST + r0] = make_float4(v0, v1, v2, v3);
    }
    __syncthreads();

    const int f0 = w << 2;  // warp owns features f0..f0+3; f&3 == ff -> constexpr shifts
    if (tile != NTILES - 1) {
        { const int f = f0;     feat_fast<0,1>(s_x + f*ST, s_m2 + f*SM2, out + (size_t)((b<<5)+f)*OUT_PER, t0, lane, invT); }
        { const int f = f0 + 1; feat_fast<3,0>(s_x + f*ST, s_m2 + f*SM2, out + (size_t)((b<<5)+f)*OUT_PER, t0, lane, invT); }
        { const int f = f0 + 2; feat_fast<2,3>(s_x + f*ST, s_m2 + f*SM2, out + (size_t)((b<<5)+f)*OUT_PER, t0, lane, invT); }
        { const int f = f0 + 3; feat_fast<1,2>(s_x + f*ST, s_m2 + f*SM2, out + (size_t)((b<<5)+f)*OUT_PER, t0, lane, invT); }
    } else {
        #pragma unroll
        for (int ff = 0; ff < 4; ff++) {
            const int f = f0 + ff;
            feat_slow(s_x + f*ST, s_m2 + f*SM2, out + (size_t)((b<<5)+f)*OUT_PER, t0, lane, invT);
        }
    }
}

extern "C" void kernel_launch(void* const* d_in, const int* in_sizes, int n_in,
                              void* d_out, int out_size) {
    const float* x = (const float*)d_in[0];
    float* out = (float*)d_out;
    wavelet_kernel<<<B * NTILES, 256>>>(x, out);
}

// round 6
// speedup vs baseline: 1.5961x; 1.0265x over previous
#include <cuda_runtime.h>

// WaveletTransformLayer: x (B=128, T=2048, F=32) fp32.
// 3-level moving-average pyramid (w = 2, 4, 8) per (b,f) series.
// Fast path: lane owns an ALIGNED run of 4 outputs per section (alignment
// shift oA/oB is compile-time per f&3), so all output stores are STG.128
// and all smem reads are LDS.128 — minimal L1 wavefronts. Last tile uses a
// scalar fallback for boundary gating.

constexpr int B = 128;
constexpr int T = 2048;
constexpr int F = 32;

constexpr int N1 = T - 1;                  // 2047
constexpr int N2 = N1 - 3;                 // 2044
constexpr int N3 = N2 - 7;                 // 2037
constexpr int OUT_PER = N1 + N2 + 2 * N3;  // 8165

constexpr int TT = 128;                    // time-tile
constexpr int NTILES = T / TT;             // 16
constexpr int XG = 37;                     // x float4-groups per row: fills [0,148)
constexpr int ST = 156;                    // s_x row stride (16B-aligned, ==4 mod 8)
constexpr int SM2 = 140;                   // s_m2 row stride (16B-aligned, ==4 mod 8)

// Store a float4-run at aligned offset O (compile-time). Lanes 0..30 vector;
// lane 31 stores only the in-range first 4-O components; O==0 -> all vector.
template<int O>
__device__ __forceinline__ void store_vec(float* __restrict__ sec, int lane, const float4& v) {
    if (O == 0) {
        *reinterpret_cast<float4*>(sec + 4 * lane) = v;
    } else {
        const float* pv = &v.x;
        if (lane < 31) {
            *reinterpret_cast<float4*>(sec + O + 4 * lane) = v;
        } else {
            #pragma unroll
            for (int c = 0; c < 4 - O; c++) sec[O + 124 + c] = pv[c];
        }
    }
}

template<int OA, int OB>
__device__ __forceinline__ void feat_fast(const float* __restrict__ rx,
                                          float* __restrict__ rm,
                                          float* __restrict__ op,
                                          int t0, int lane, float invT) {
    const float hInvT = 0.5f * invT;

    // ---- Pass A: window x[4l .. 4l+12) ----
    float xw[12];
    *(float4*)&xw[0] = *(const float4*)(rx + 4 * lane);
    *(float4*)&xw[4] = *(const float4*)(rx + 4 * lane + 4);
    *(float4*)&xw[8] = *(const float4*)(rx + 4 * lane + 8);

    // aligned m2 group g = lane  (m2[j] = (x[j]+x[j+4]+2(x[j+1..j+3]))/8)
    {
        float4 m; float* pm = &m.x;
        #pragma unroll
        for (int c = 0; c < 4; c++)
            pm[c] = (xw[c] + xw[c + 4] + 2.0f * ((xw[c + 1] + xw[c + 2]) + xw[c + 3])) * 0.125f;
        *(float4*)(rm + 4 * lane) = m;
    }
    // extra m2 groups 32..34 (halo for pass B windows, up to m2[139])
    if (lane < 3) {
        const int g = 32 + lane;
        float xe[12];
        *(float4*)&xe[0] = *(const float4*)(rx + 4 * g);
        *(float4*)&xe[4] = *(const float4*)(rx + 4 * g + 4);
        *(float4*)&xe[8] = *(const float4*)(rx + 4 * g + 8);
        float4 m; float* pm = &m.x;
        #pragma unroll
        for (int c = 0; c < 4; c++)
            pm[c] = (xe[c] + xe[c + 4] + 2.0f * ((xe[c + 1] + xe[c + 2]) + xe[c + 3])) * 0.125f;
        *(float4*)(rm + 4 * g) = m;
    }

    // d1 at shift OA: d1[j] = (x[j+1]-x[j])/2
    {
        float4 v; float* pv = &v.x;
        #pragma unroll
        for (int c = 0; c < 4; c++)
            pv[c] = (xw[OA + c + 1] - xw[OA + c]) * hInvT;
        store_vec<OA>(op + t0, lane, v);
        if (OA > 0 && lane == 0) {
            #pragma unroll
            for (int c = 0; c < OA; c++)
                op[t0 + c] = (xw[c + 1] - xw[c]) * hInvT;
        }
    }
    // d2 at shift OB: d2[j] = (x[j+3]+x[j+4])/2 - m2[j]
    {
        float4 v; float* pv = &v.x;
        #pragma unroll
        for (int c = 0; c < 4; c++) {
            float m2s = (xw[OB + c] + xw[OB + c + 4]
                       + 2.0f * ((xw[OB + c + 1] + xw[OB + c + 2]) + xw[OB + c + 3])) * 0.125f;
            pv[c] = ((xw[OB + c + 3] + xw[OB + c + 4]) * 0.5f - m2s) * invT;
        }
        store_vec<OB>(op + N1 + t0, lane, v);
        if (OB > 0 && lane == 0) {
            #pragma unroll
            for (int c = 0; c < OB; c++) {
                float m2s = (xw[c] + xw[c + 4]
                           + 2.0f * ((xw[c + 1] + xw[c + 2]) + xw[c + 3])) * 0.125f;
                op[N1 + t0 + c] = ((xw[c + 3] + xw[c + 4]) * 0.5f - m2s) * invT;
            }
        }
    }
    __syncwarp();

    // ---- Pass B: window m2[4l .. 4l+12/16) ----
    constexpr int MAXO = (OA > OB) ? OA : OB;
    constexpr int MINO = (OA < OB) ? OA : OB;
    constexpr int NW = (MAXO >= 2) ? 16 : 12;
    float mw[NW];
    *(float4*)&mw[0] = *(const float4*)(rm + 4 * lane);
    *(float4*)&mw[4] = *(const float4*)(rm + 4 * lane + 4);
    *(float4*)&mw[8] = *(const float4*)(rm + 4 * lane + 8);
    if constexpr (MAXO >= 2)
        *(float4*)&mw[12] = *(const float4*)(rm + 4 * lane + 12);

    // sliding window-8 sums for positions MINO .. MAXO+3
    constexpr int NS = MAXO + 3 - MINO + 1;
    float s[NS];
    s[0] = ((mw[MINO] + mw[MINO + 1]) + (mw[MINO + 2] + mw[MINO + 3]))
         + ((mw[MINO + 4] + mw[MINO + 5]) + (mw[MINO + 6] + mw[MINO + 7]));
    #pragma unroll
    for (int i = 1; i < NS; i++)
        s[i] = s[i - 1] + mw[MINO + i + 7] - mw[MINO + i - 1];

    // d3 at shift OB: d3[j] = m2[j+7] - sum8/8
    {
        float4 v; float* pv = &v.x;
        #pragma unroll
        for (int c = 0; c < 4; c++)
            pv[c] = (mw[OB + c + 7] - s[OB + c - MINO] * 0.125f) * invT;
        store_vec<OB>(op + N1 + N2 + t0, lane, v);
        if (OB > 0 && lane == 0) {
            #pragma unroll
            for (int c = 0; c < OB; c++) {
                float sh = ((mw[c] + mw[c + 1]) + (mw[c + 2] + mw[c + 3]))
                         + ((mw[c + 4] + mw[c + 5]) + (mw[c + 6] + mw[c + 7]));
                op[N1 + N2 + t0 + c] = (mw[c + 7] - sh * 0.125f) * invT;
            }
        }
    }
    // a3 at shift OA: sum8/8
    {
        float4 v; float* pv = &v.x;
        #pragma unroll
        for (int c = 0; c < 4; c++)
            pv[c] = s[OA + c - MINO] * 0.125f * invT;
        store_vec<OA>(op + N1 + N2 + N3 + t0, lane, v);
        if (OA > 0 && lane == 0) {
            #pragma unroll
            for (int c = 0; c < OA; c++) {
                float sh = ((mw[c] + mw[c + 1]) + (mw[c + 2] + mw[c + 3]))
                         + ((mw[c + 4] + mw[c + 5]) + (mw[c + 6] + mw[c + 7]));
                op[N1 + N2 + N3 + t0 + c] = sh * 0.125f * invT;
            }
        }
    }
}

// Scalar fallback for the last tile (boundary gating), R3-style coalesced.
__device__ void feat_slow(const float* __restrict__ rx, float* __restrict__ rm,
                          float* __restrict__ op, int t0, int lane, float invT) {
    const float h = 0.5f * invT;
    for (int j = lane; j < N1 - t0; j += 32)
        op[t0 + j] = (rx[j + 1] - rx[j]) * h;
    for (int j = lane; j < N2 - t0; j += 32) {
        float m2 = (rx[j] + rx[j + 4] + 2.0f * ((rx[j + 1] + rx[j + 2]) + rx[j + 3])) * 0.125f;
        rm[j] = m2;
        op[N1 + t0 + j] = ((rx[j + 3] + rx[j + 4]) * 0.5f - m2) * invT;
    }
    __syncwarp();
    for (int j = lane; j < N3 - t0; j += 32) {
        float ss = ((rm[j] + rm[j + 1]) + (rm[j + 2] + rm[j + 3]))
                 + ((rm[j + 4] + rm[j + 5]) + (rm[j + 6] + rm[j + 7]));
        float m3 = ss * 0.125f;
        op[N1 + N2 + t0 + j]      = (rm[j + 7] - m3) * invT;
        op[N1 + N2 + N3 + t0 + j] = m3 * invT;
    }
}

__global__ __launch_bounds__(256, 5)
void wavelet_kernel(const float* __restrict__ x, float* __restrict__ out) {
    __shared__ float s_x[F * ST];
    __shared__ float s_m2[F * SM2];

    const int tile = blockIdx.x & (NTILES - 1);
    const int b    = blockIdx.x >> 4;
    const int t0   = tile * TT;
    const int lane = threadIdx.x & 31;
    const int w    = threadIdx.x >> 5;
    const float invT = 1.0f / (float)T;

    // Coalesced load + float4 transpose: rows = time, lane = feature.
    const float* xp = x + ((size_t)b * T + t0) * F;
    for (int g = w; g < XG; g += 8) {
        const int r0 = 4 * g;
        float v0 = (t0 + r0     < T) ? xp[(size_t)(r0    ) * F + lane] : 0.0f;
        float v1 = (t0 + r0 + 1 < T) ? xp[(size_t)(r0 + 1) * F + lane] : 0.0f;
        float v2 = (t0 + r0 + 2 < T) ? xp[(size_t)(r0 + 2) * F + lane] : 0.0f;
        float v3 = (t0 + r0 + 3 < T) ? xp[(size_t)(r0 + 3) * F + lane] : 0.0f;
        *(float4*)&s_x[lane * ST + r0] = make_float4(v0, v1, v2, v3);
    }
    __syncthreads();

    const int f0 = w << 2;  // warp owns features f0..f0+3; f&3 == ff -> constexpr shifts
    if (tile != NTILES - 1) {
        { const int f = f0;     feat_fast<0,1>(s_x + f*ST, s_m2 + f*SM2, out + (size_t)((b<<5)+f)*OUT_PER, t0, lane, invT); }
        { const int f = f0 + 1; feat_fast<3,0>(s_x + f*ST, s_m2 + f*SM2, out + (size_t)((b<<5)+f)*OUT_PER, t0, lane, invT); }
        { const int f = f0 + 2; feat_fast<2,3>(s_x + f*ST, s_m2 + f*SM2, out + (size_t)((b<<5)+f)*OUT_PER, t0, lane, invT); }
        { const int f = f0 + 3; feat_fast<1,2>(s_x + f*ST, s_m2 + f*SM2, out + (size_t)((b<<5)+f)*OUT_PER, t0, lane, invT); }
    } else {
        #pragma unroll
        for (int ff = 0; ff < 4; ff++) {
            const int f = f0 + ff;
            feat_slow(s_x + f*ST, s_m2 + f*SM2, out + (size_t)((b<<5)+f)*OUT_PER, t0, lane, invT);
        }
    }
}

extern "C" void kernel_launch(void* const* d_in, const int* in_sizes, int n_in,
                              void* d_out, int out_size) {
    const float* x = (const float*)d_in[0];
    float* out = (float*)d_out;
    wavelet_kernel<<<B * NTILES, 256>>>(x, out);
}